// round 15
// baseline (speedup 1.0000x reference)
#include <cuda_runtime.h>
#include <cuda_bf16.h>
#include <math.h>

#define NN 50000
#define EE 600000
#define DD 128
#define NF (NN*DD)
#define NBLK 196   // ceil(NN/256)

// ---------------------------------------------------------------------------
__device__ __forceinline__ unsigned packbf(float even, float odd) {
    unsigned d;
    asm("cvt.rn.bf16x2.f32 %0, %1, %2;" : "=r"(d) : "f"(odd), "f"(even));
    return d;
}
__device__ __forceinline__ float bfres(float v) {
    return v - __bfloat162float(__float2bfloat16(v));
}
__device__ __forceinline__ void mma_bf16(
    float& d0, float& d1, float& d2, float& d3,
    unsigned a0, unsigned a1, unsigned a2, unsigned a3,
    unsigned b0, unsigned b1) {
    asm volatile(
        "mma.sync.aligned.m16n8k16.row.col.f32.bf16.bf16.f32 "
        "{%0,%1,%2,%3},{%4,%5,%6,%7},{%8,%9},{%0,%1,%2,%3};"
        : "+f"(d0), "+f"(d1), "+f"(d2), "+f"(d3)
        : "r"(a0), "r"(a1), "r"(a2), "r"(a3), "r"(b0), "r"(b1));
}

// ---------------------------------------------------------------------------
#define OFF_AGG1B 0ULL
#define OFF_AGG1A (1ULL*NF)
#define OFF_AGG2B (2ULL*NF)
#define OFF_AGG2A (3ULL*NF)
#define OFF_HB    (4ULL*NF)
#define OFF_HA    (5ULL*NF)
#define OFF_H2A   (6ULL*NF)   // packed: hi plane [NN*64 u32], lo plane at +NN*64
#define OFF_H2B   (7ULL*NF)
#define OFF_HMLP  (8ULL*NF)
#define OFF_RS    (9ULL*NF)
#define OFF_STATS (9ULL*NF + 4ULL*NN)
#define OFF_BN    (OFF_STATS + 256ULL)
#define OFF_WT    (OFF_BN + 256ULL)
#define SCRATCH_FLOATS (OFF_WT + 196608ULL)

__device__ __align__(256) float g_s[SCRATCH_FLOATS];

#define IOFF_EIDX0 0
#define IOFF_EIDX1 (EE)
#define IOFF_OD0   (2*EE)
#define IOFF_CNT0  (2*EE + NN)
#define IOFF_OD1   (2*EE + 2*NN)
#define IOFF_CNT1  (2*EE + 3*NN)
#define IOFF_RP0   (2*EE + 4*NN)
#define IOFF_RP1   (2*EE + 5*NN + 1)
#define IOFF_CUR0  (2*EE + 6*NN + 2)
#define IOFF_CUR1  (2*EE + 7*NN + 2)
#define IOFF_BSUM  (2*EE + 8*NN + 2)
#define IOFF_PFX   (IOFF_BSUM + 2*NBLK)
// syn: [0,1]=rel0 scan, [2,3]=rel1 scan, [4]=mlp1 arrivals
#define IOFF_SYNC  (IOFF_PFX + 2*NBLK)
#define SCRATCH_INTS (IOFF_SYNC + 8)

__device__ __align__(256) int g_i[SCRATCH_INTS];

// ---------------------------------------------------------------------------
__global__ void k_zero2(int* __restrict__ deg, float* __restrict__ stats,
                        int* __restrict__ syn) {
    int i = blockIdx.x * 256 + threadIdx.x;
    if (i < NN) ((int4*)deg)[i] = make_int4(0, 0, 0, 0);
    if (i < 64) ((float4*)stats)[i] = make_float4(0.f, 0.f, 0.f, 0.f);
    if (i < 8) syn[i] = 0;
}

__global__ void k_hist_r(const int* __restrict__ s, const int* __restrict__ d,
                         int* __restrict__ od, int* __restrict__ cnt) {
    int i = blockIdx.x * blockDim.x + threadIdx.x;
    if (i < EE) {
        atomicAdd(&od[s[i]], 1);
        atomicAdd(&cnt[d[i]], 1);
    }
}

__global__ void k_wprep(const float* __restrict__ W1r0, const float* __restrict__ W1r1,
                        const float* __restrict__ W2r0, const float* __restrict__ W2r1,
                        const float* __restrict__ Wm1, unsigned* __restrict__ WT) {
    int idx = blockIdx.x * 256 + threadIdx.x;
    if (idx < 32768) {
        int mat = idx >> 13, r = idx & 8191;
        int n = r >> 6, ku = r & 63;
        int k = 2 * ku;
        const float* Wsrc = (mat == 0) ? W1r0 : (mat == 1) ? W1r1 :
                            (mat == 2) ? W2r0 : W2r1;
        float v0 = __ldg(Wsrc + k * 128 + n);
        float v1 = __ldg(Wsrc + (k + 1) * 128 + n);
        WT[mat * 16384 + n * 64 + ku]        = packbf(v0, v1);
        WT[mat * 16384 + 8192 + n * 64 + ku] = packbf(bfres(v0), bfres(v1));
    } else if (idx < 49152) {
        int r = idx - 32768;
        int n = r >> 7, ku = r & 127;
        int k = 2 * ku;
        float v0 = __ldg(Wm1 + k * 128 + n);
        float v1 = __ldg(Wm1 + (k + 1) * 128 + n);
        WT[65536 + n * 128 + ku]         = packbf(v0, v1);
        WT[65536 + 16384 + n * 128 + ku] = packbf(bfres(v0), bfres(v1));
    }
}

__global__ void __launch_bounds__(256) k_scan_r(
    const int* __restrict__ cnt, const int* __restrict__ od,
    int* __restrict__ bsum, int* __restrict__ pfx,
    int* __restrict__ arr, int* __restrict__ flag,
    int* __restrict__ rp, int* __restrict__ cur,
    float* __restrict__ rs_src, float* __restrict__ rs_dst) {
    __shared__ int sp[256];
    __shared__ int islast;
    int t = threadIdx.x;
    int i = blockIdx.x * 256 + t;
    int v = (i < NN) ? cnt[i] : 0;

    sp[t] = v;
    __syncthreads();
    for (int off = 128; off; off >>= 1) {
        if (t < off) sp[t] += sp[t + off];
        __syncthreads();
    }
    if (t == 0) {
        bsum[blockIdx.x] = sp[0];
        __threadfence();
        int old = atomicAdd(arr, 1);
        islast = (old == NBLK - 1);
    }
    __syncthreads();

    if (islast) {
        int mine = (t < NBLK) ? ((volatile int*)bsum)[t] : 0;
        sp[t] = mine;
        __syncthreads();
        for (int off = 1; off < 256; off <<= 1) {
            int u = (t >= off) ? sp[t - off] : 0;
            __syncthreads();
            sp[t] += u;
            __syncthreads();
        }
        if (t < NBLK) pfx[t] = sp[t] - mine;
        __syncthreads();
        if (t == 0) {
            __threadfence();
            atomicExch(flag, 1);
        }
    }
    if (t == 0) {
        while (((volatile int*)flag)[0] == 0) __nanosleep(64);
    }
    __syncthreads();

    sp[t] = v;
    __syncthreads();
    for (int off = 1; off < 256; off <<= 1) {
        int u = (t >= off) ? sp[t - off] : 0;
        __syncthreads();
        sp[t] += u;
        __syncthreads();
    }
    if (i < NN) {
        int ex = sp[t] - v + ((volatile int*)pfx)[blockIdx.x];
        rp[i] = ex;
        cur[i] = ex;
        rs_src[i] = rsqrtf((float)max(od[i], 1));
        rs_dst[i] = rsqrtf((float)max(v, 1));
    }
    if (i == NN - 1) rp[NN] = EE;
}

__global__ void k_fill_r(const int* __restrict__ s, const int* __restrict__ d,
                         int* __restrict__ cur, int* __restrict__ eidx) {
    int i = blockIdx.x * blockDim.x + threadIdx.x;
    if (i < EE) {
        int p = atomicAdd(&cur[d[i]], 1);
        eidx[p] = s[i];
    }
}

// ---------------------------------------------------------------------------
// gather -> PACKED bf16 hi/lo AGG (R14-exact)
__global__ void __launch_bounds__(256, 8) k_gather_pk(
    const float* __restrict__ x, const int* __restrict__ eidx,
    const int* __restrict__ rowptr, const float* __restrict__ rs_src,
    const float* __restrict__ rs_row, uint4* __restrict__ aggp, int useRs) {
    int g = blockIdx.x * blockDim.x + threadIdx.x;
    int r = g >> 5, lane = g & 31;
    if (r >= NN) return;
    int beg = __ldg(rowptr + r), end = __ldg(rowptr + r + 1);
    float4 acc = make_float4(0.f, 0.f, 0.f, 0.f);
    int e = beg;
    if (useRs) {
        for (; e + 1 < end; e += 2) {
            int sa = __ldg(eidx + e), sb = __ldg(eidx + e + 1);
            float ra = __ldg(rs_src + sa), rb = __ldg(rs_src + sb);
            float4 va = __ldg((const float4*)(x + (long)sa * DD) + lane);
            float4 vb = __ldg((const float4*)(x + (long)sb * DD) + lane);
            acc.x = fmaf(va.x, ra, acc.x); acc.y = fmaf(va.y, ra, acc.y);
            acc.z = fmaf(va.z, ra, acc.z); acc.w = fmaf(va.w, ra, acc.w);
            acc.x = fmaf(vb.x, rb, acc.x); acc.y = fmaf(vb.y, rb, acc.y);
            acc.z = fmaf(vb.z, rb, acc.z); acc.w = fmaf(vb.w, rb, acc.w);
        }
        if (e < end) {
            int sa = __ldg(eidx + e);
            float ra = __ldg(rs_src + sa);
            float4 va = __ldg((const float4*)(x + (long)sa * DD) + lane);
            acc.x = fmaf(va.x, ra, acc.x); acc.y = fmaf(va.y, ra, acc.y);
            acc.z = fmaf(va.z, ra, acc.z); acc.w = fmaf(va.w, ra, acc.w);
        }
    } else {
        for (; e + 1 < end; e += 2) {
            int sa = __ldg(eidx + e), sb = __ldg(eidx + e + 1);
            float4 va = __ldg((const float4*)(x + (long)sa * DD) + lane);
            float4 vb = __ldg((const float4*)(x + (long)sb * DD) + lane);
            acc.x += va.x + vb.x; acc.y += va.y + vb.y;
            acc.z += va.z + vb.z; acc.w += va.w + vb.w;
        }
        if (e < end) {
            int sa = __ldg(eidx + e);
            float4 va = __ldg((const float4*)(x + (long)sa * DD) + lane);
            acc.x += va.x; acc.y += va.y; acc.z += va.z; acc.w += va.w;
        }
    }
    float rd = __ldg(rs_row + r);
    acc.x *= rd; acc.y *= rd; acc.z *= rd; acc.w *= rd;
    unsigned h0 = packbf(acc.x, acc.y), h1 = packbf(acc.z, acc.w);
    unsigned l0 = packbf(bfres(acc.x), bfres(acc.y));
    unsigned l1 = packbf(bfres(acc.z), bfres(acc.w));
    aggp[(long)r * 32 + lane] = make_uint4(h0, h1, l0, l1);
}

// ---------------------------------------------------------------------------
// bf16x3 GEMM on PACKED A. Output: float (out!=null, rso/relu applied) or
// packed bf16 hi/lo planes (outp!=null; hi at [r*64+c/2], lo at +NN*64).
#define U_AHI 0
#define U_ALO 4352
#define U_WHI 8704
#define U_WLO 17408
#define SMEM_G ((size_t)26112 * 4)

__global__ void __launch_bounds__(256, 2) k_gemm_bf16(
    const uint4* __restrict__ Xp,
    const unsigned* __restrict__ Wp, const float* __restrict__ bp,
    float* __restrict__ out, const float* __restrict__ rso,
    unsigned* __restrict__ outp, int doRelu) {
    extern __shared__ unsigned smu[];
    unsigned* sAhi = smu + U_AHI;
    unsigned* sAlo = smu + U_ALO;
    unsigned* sWhi = smu + U_WHI;
    unsigned* sWlo = smu + U_WLO;

    int tid = threadIdx.x;
    int r0 = blockIdx.x * 64;

    for (int i = tid; i < 2048; i += 256) {
        int row = i >> 5, f4 = i & 31;
        int gr = r0 + row;
        uint4 p = make_uint4(0u, 0u, 0u, 0u);
        if (gr < NN) p = __ldg(Xp + (long)gr * 32 + f4);
        ((uint2*)(sAhi + row * 68))[f4] = make_uint2(p.x, p.y);
        ((uint2*)(sAlo + row * 68))[f4] = make_uint2(p.z, p.w);
    }
    for (int i = tid; i < 4096; i += 256) {
        int n = i >> 5, q = i & 31;
        ((uint2*)(sWhi + n * 68))[q] = __ldg((const uint2*)(Wp + n * 64) + q);
        ((uint2*)(sWlo + n * 68))[q] = __ldg((const uint2*)(Wp + 8192 + n * 64) + q);
    }
    __syncthreads();

    int lane = tid & 31, w = tid >> 5;
    int mg = w >> 2, ng = w & 3;
    int tg = lane & 3, gid = lane >> 2;

    float acc[2][4][4];
#pragma unroll
    for (int mi = 0; mi < 2; mi++)
#pragma unroll
        for (int ni = 0; ni < 4; ni++)
#pragma unroll
            for (int q = 0; q < 4; q++) acc[mi][ni][q] = 0.f;

#pragma unroll
    for (int ks = 0; ks < 8; ks++) {
        unsigned Ah[2][4], Al[2][4], Bh[4][2], Bl[4][2];
#pragma unroll
        for (int mi = 0; mi < 2; mi++) {
            int base = (mg * 32 + mi * 16 + gid) * 68 + ks * 8 + tg;
            Ah[mi][0] = sAhi[base];
            Ah[mi][1] = sAhi[base + 8 * 68];
            Ah[mi][2] = sAhi[base + 4];
            Ah[mi][3] = sAhi[base + 8 * 68 + 4];
            Al[mi][0] = sAlo[base];
            Al[mi][1] = sAlo[base + 8 * 68];
            Al[mi][2] = sAlo[base + 4];
            Al[mi][3] = sAlo[base + 8 * 68 + 4];
        }
#pragma unroll
        for (int ni = 0; ni < 4; ni++) {
            int cb = (ng * 32 + ni * 8 + gid) * 68 + ks * 8 + tg;
            Bh[ni][0] = sWhi[cb];
            Bh[ni][1] = sWhi[cb + 4];
            Bl[ni][0] = sWlo[cb];
            Bl[ni][1] = sWlo[cb + 4];
        }
#pragma unroll
        for (int mi = 0; mi < 2; mi++)
#pragma unroll
            for (int ni = 0; ni < 4; ni++) {
                float* d = acc[mi][ni];
                mma_bf16(d[0], d[1], d[2], d[3],
                         Ah[mi][0], Ah[mi][1], Ah[mi][2], Ah[mi][3],
                         Bh[ni][0], Bh[ni][1]);
                mma_bf16(d[0], d[1], d[2], d[3],
                         Ah[mi][0], Ah[mi][1], Ah[mi][2], Ah[mi][3],
                         Bl[ni][0], Bl[ni][1]);
                mma_bf16(d[0], d[1], d[2], d[3],
                         Al[mi][0], Al[mi][1], Al[mi][2], Al[mi][3],
                         Bh[ni][0], Bh[ni][1]);
            }
    }

#pragma unroll
    for (int ni = 0; ni < 4; ni++) {
        int col = ng * 32 + ni * 8 + 2 * tg;
        float bb0 = __ldg(bp + col), bb1 = __ldg(bp + col + 1);
#pragma unroll
        for (int mi = 0; mi < 2; mi++) {
            int gr = r0 + mg * 32 + mi * 16 + gid;
            if (gr < NN) {
                float v0 = acc[mi][ni][0] + bb0;
                float v1 = acc[mi][ni][1] + bb1;
                if (outp) {
                    outp[(long)gr * 64 + (col >> 1)] = packbf(v0, v1);
                    outp[(long)NN * 64 + (long)gr * 64 + (col >> 1)] =
                        packbf(bfres(v0), bfres(v1));
                } else {
                    float ro = rso ? __ldg(rso + gr) : 1.f;
                    if (doRelu) { v0 = fmaxf(v0, 0.f); v1 = fmaxf(v1, 0.f); }
                    *(float2*)(out + (long)gr * DD + col) = make_float2(v0 * ro, v1 * ro);
                }
            }
            int gr8 = gr + 8;
            if (gr8 < NN) {
                float v2 = acc[mi][ni][2] + bb0;
                float v3 = acc[mi][ni][3] + bb1;
                if (outp) {
                    outp[(long)gr8 * 64 + (col >> 1)] = packbf(v2, v3);
                    outp[(long)NN * 64 + (long)gr8 * 64 + (col >> 1)] =
                        packbf(bfres(v2), bfres(v3));
                } else {
                    float ro = rso ? __ldg(rso + gr8) : 1.f;
                    if (doRelu) { v2 = fmaxf(v2, 0.f); v3 = fmaxf(v3, 0.f); }
                    *(float2*)(out + (long)gr8 * DD + col) = make_float2(v2 * ro, v3 * ro);
                }
            }
        }
    }
}

// ---------------------------------------------------------------------------
// MLP layer1 on PACKED H2 inputs + BN stats + last-block BN finalize
__global__ void __launch_bounds__(256, 2) k_mlp1_bf16(
    const unsigned* __restrict__ XAp, const unsigned* __restrict__ XBp,
    const unsigned* __restrict__ WTm1, float* __restrict__ out,
    float* __restrict__ stat, int* __restrict__ syn,
    const float* __restrict__ gamma, const float* __restrict__ beta,
    float* __restrict__ bn) {
    extern __shared__ unsigned smu[];
    unsigned* sAhi = smu + U_AHI;
    unsigned* sAlo = smu + U_ALO;
    unsigned* sWhi = smu + U_WHI;
    unsigned* sWlo = smu + U_WLO;
    int tid = threadIdx.x;
    int r0 = blockIdx.x * 64;
    int lane = tid & 31, w = tid >> 5;
    int mg = w >> 2, ng = w & 3;
    int tg = lane & 3, gid = lane >> 2;

    float acc[2][4][4];
#pragma unroll
    for (int mi = 0; mi < 2; mi++)
#pragma unroll
        for (int ni = 0; ni < 4; ni++)
#pragma unroll
            for (int q = 0; q < 4; q++) acc[mi][ni][q] = 0.f;

    for (int ph = 0; ph < 2; ph++) {
        const unsigned* Xp = ph ? XBp : XAp;
        for (int i = tid; i < 2048; i += 256) {
            int row = i >> 5, f4 = i & 31;
            int gr = r0 + row;
            uint2 h = make_uint2(0u, 0u), l = make_uint2(0u, 0u);
            if (gr < NN) {
                h = __ldg((const uint2*)(Xp + (long)gr * 64) + f4);
                l = __ldg((const uint2*)(Xp + (long)NN * 64 + (long)gr * 64) + f4);
            }
            ((uint2*)(sAhi + row * 68))[f4] = h;
            ((uint2*)(sAlo + row * 68))[f4] = l;
        }
        for (int i = tid; i < 4096; i += 256) {
            int n = i >> 5, q = i & 31;
            ((uint2*)(sWhi + n * 68))[q] =
                __ldg((const uint2*)(WTm1 + n * 128 + ph * 64) + q);
            ((uint2*)(sWlo + n * 68))[q] =
                __ldg((const uint2*)(WTm1 + 16384 + n * 128 + ph * 64) + q);
        }
        __syncthreads();

#pragma unroll
        for (int ks = 0; ks < 8; ks++) {
            unsigned Ah[2][4], Al[2][4], Bh[4][2], Bl[4][2];
#pragma unroll
            for (int mi = 0; mi < 2; mi++) {
                int base = (mg * 32 + mi * 16 + gid) * 68 + ks * 8 + tg;
                Ah[mi][0] = sAhi[base];
                Ah[mi][1] = sAhi[base + 8 * 68];
                Ah[mi][2] = sAhi[base + 4];
                Ah[mi][3] = sAhi[base + 8 * 68 + 4];
                Al[mi][0] = sAlo[base];
                Al[mi][1] = sAlo[base + 8 * 68];
                Al[mi][2] = sAlo[base + 4];
                Al[mi][3] = sAlo[base + 8 * 68 + 4];
            }
#pragma unroll
            for (int ni = 0; ni < 4; ni++) {
                int cb = (ng * 32 + ni * 8 + gid) * 68 + ks * 8 + tg;
                Bh[ni][0] = sWhi[cb];
                Bh[ni][1] = sWhi[cb + 4];
                Bl[ni][0] = sWlo[cb];
                Bl[ni][1] = sWlo[cb + 4];
            }
#pragma unroll
            for (int mi = 0; mi < 2; mi++)
#pragma unroll
                for (int ni = 0; ni < 4; ni++) {
                    float* d = acc[mi][ni];
                    mma_bf16(d[0], d[1], d[2], d[3],
                             Ah[mi][0], Ah[mi][1], Ah[mi][2], Ah[mi][3],
                             Bh[ni][0], Bh[ni][1]);
                    mma_bf16(d[0], d[1], d[2], d[3],
                             Ah[mi][0], Ah[mi][1], Ah[mi][2], Ah[mi][3],
                             Bl[ni][0], Bl[ni][1]);
                    mma_bf16(d[0], d[1], d[2], d[3],
                             Al[mi][0], Al[mi][1], Al[mi][2], Al[mi][3],
                             Bh[ni][0], Bh[ni][1]);
                }
        }
        __syncthreads();
    }

    float cs[4][2], cq[4][2];
#pragma unroll
    for (int ni = 0; ni < 4; ni++) {
        cs[ni][0] = cs[ni][1] = 0.f;
        cq[ni][0] = cq[ni][1] = 0.f;
    }
#pragma unroll
    for (int ni = 0; ni < 4; ni++) {
        int col = ng * 32 + ni * 8 + 2 * tg;
#pragma unroll
        for (int mi = 0; mi < 2; mi++) {
            int gr = r0 + mg * 32 + mi * 16 + gid;
            if (gr < NN) {
                float v0 = acc[mi][ni][0], v1 = acc[mi][ni][1];
                *(float2*)(out + (long)gr * DD + col) = make_float2(v0, v1);
                cs[ni][0] += v0; cq[ni][0] += v0 * v0;
                cs[ni][1] += v1; cq[ni][1] += v1 * v1;
            }
            int gr8 = gr + 8;
            if (gr8 < NN) {
                float v2 = acc[mi][ni][2], v3 = acc[mi][ni][3];
                *(float2*)(out + (long)gr8 * DD + col) = make_float2(v2, v3);
                cs[ni][0] += v2; cq[ni][0] += v2 * v2;
                cs[ni][1] += v3; cq[ni][1] += v3 * v3;
            }
        }
    }
    __syncthreads();
    float* ssum = (float*)smu;
    float* ssq  = (float*)smu + 128;
    if (tid < 256) ((float*)smu)[tid] = 0.f;
    __syncthreads();
#pragma unroll
    for (int ni = 0; ni < 4; ni++) {
        int col = ng * 32 + ni * 8 + 2 * tg;
        atomicAdd(&ssum[col], cs[ni][0]);
        atomicAdd(&ssum[col + 1], cs[ni][1]);
        atomicAdd(&ssq[col], cq[ni][0]);
        atomicAdd(&ssq[col + 1], cq[ni][1]);
    }
    __syncthreads();
    if (tid < 128) {
        atomicAdd(&stat[tid], ssum[tid]);
        atomicAdd(&stat[128 + tid], ssq[tid]);
    }

    __shared__ int lastblk;
    __threadfence();
    __syncthreads();
    if (tid == 0) {
        int old = atomicAdd(&syn[4], 1);
        lastblk = (old == (int)gridDim.x - 1);
    }
    __syncthreads();
    if (lastblk && tid < 128) {
        float s  = atomicAdd(&stat[tid], 0.f);
        float sq = atomicAdd(&stat[128 + tid], 0.f);
        float mu  = s * (1.f / NN);
        float var = sq * (1.f / NN) - mu * mu;
        float sc  = __ldg(gamma + tid) * rsqrtf(var + 1e-5f);
        bn[tid]       = sc;
        bn[128 + tid] = __ldg(beta + tid) - mu * sc;
    }
}

// ---------------------------------------------------------------------------
__global__ void __launch_bounds__(256) k_mlp2(
    const float* __restrict__ H, const float* __restrict__ bn,
    const float* __restrict__ Wm2, float* __restrict__ out) {
    __shared__ float sw[256];
    __shared__ float sb[256];
    int tid = threadIdx.x;
    if (tid < 256) { sw[tid] = Wm2[tid]; sb[tid] = bn[tid]; }
    __syncthreads();
    int g = blockIdx.x * blockDim.x + tid;
    int row = g >> 5, lane = g & 31;
    if (row >= NN) return;
    float4 h = ((const float4*)(H + (long)row * DD))[lane];
    float s0 = 0.f, s1 = 0.f;
    int c = lane * 4;
    float hv[4] = {h.x, h.y, h.z, h.w};
#pragma unroll
    for (int j = 0; j < 4; j++) {
        int cc = c + j;
        float v = fmaxf(hv[j] * sb[cc] + sb[128 + cc], 0.f);
        s0 += v * sw[cc * 2];
        s1 += v * sw[cc * 2 + 1];
    }
#pragma unroll
    for (int off = 16; off > 0; off >>= 1) {
        s0 += __shfl_down_sync(0xffffffffu, s0, off);
        s1 += __shfl_down_sync(0xffffffffu, s1, off);
    }
    if (lane == 0) {
        out[row * 2]     = s0;
        out[row * 2 + 1] = s1;
    }
}

// ---------------------------------------------------------------------------
extern "C" void kernel_launch(void* const* d_in, const int* in_sizes, int n_in,
                              void* d_out, int out_size) {
    const float* xA    = (const float*)d_in[0];
    const float* xB    = (const float*)d_in[1];
    const int*   s0    = (const int*)d_in[2];
    const int*   d0    = (const int*)d_in[3];
    const int*   s1    = (const int*)d_in[4];
    const int*   d1    = (const int*)d_in[5];
    const float* W1r0  = (const float*)d_in[6];
    const float* b1r0  = (const float*)d_in[7];
    const float* W1r1  = (const float*)d_in[8];
    const float* b1r1  = (const float*)d_in[9];
    const float* W2r0  = (const float*)d_in[10];
    const float* b2r0  = (const float*)d_in[11];
    const float* W2r1  = (const float*)d_in[12];
    const float* b2r1  = (const float*)d_in[13];
    const float* Wm1   = (const float*)d_in[14];
    const float* gamma = (const float*)d_in[15];
    const float* beta  = (const float*)d_in[16];
    const float* Wm2   = (const float*)d_in[17];
    float* out = (float*)d_out;

    float* S = nullptr;
    cudaGetSymbolAddress((void**)&S, g_s);
    int* I = nullptr;
    cudaGetSymbolAddress((void**)&I, g_i);

    uint4* AGG1B = (uint4*)(S + OFF_AGG1B);
    uint4* AGG1A = (uint4*)(S + OFF_AGG1A);
    uint4* AGG2B = (uint4*)(S + OFF_AGG2B);
    uint4* AGG2A = (uint4*)(S + OFF_AGG2A);
    float* HB    = S + OFF_HB;
    float* HA    = S + OFF_HA;
    unsigned* H2Ap = (unsigned*)(S + OFF_H2A);   // packed hi/lo planes
    unsigned* H2Bp = (unsigned*)(S + OFF_H2B);
    float* HMLP  = S + OFF_HMLP;
    float* RS    = S + OFF_RS;
    float* STATS = S + OFF_STATS;
    float* BN    = S + OFF_BN;
    unsigned* WT = (unsigned*)(S + OFF_WT);

    int* eidx0 = I + IOFF_EIDX0;
    int* eidx1 = I + IOFF_EIDX1;
    int* od0   = I + IOFF_OD0;
    int* cnt0  = I + IOFF_CNT0;
    int* od1   = I + IOFF_OD1;
    int* cnt1  = I + IOFF_CNT1;
    int* rp0   = I + IOFF_RP0;
    int* rp1   = I + IOFF_RP1;
    int* cur0  = I + IOFF_CUR0;
    int* cur1  = I + IOFF_CUR1;
    int* bsum  = I + IOFF_BSUM;
    int* pfx   = I + IOFF_PFX;
    int* syn   = I + IOFF_SYNC;

    float* rs_src0 = RS + 0 * NN;
    float* rs_dst0 = RS + 1 * NN;
    float* rs_src1 = RS + 2 * NN;
    float* rs_dst1 = RS + 3 * NN;

    unsigned* W1r0T = WT + 0;
    unsigned* W1r1T = WT + 16384;
    unsigned* W2r0T = WT + 32768;
    unsigned* W2r1T = WT + 49152;
    unsigned* Wm1T  = WT + 65536;

    cudaFuncSetAttribute(k_gemm_bf16, cudaFuncAttributeMaxDynamicSharedMemorySize, (int)SMEM_G);
    cudaFuncSetAttribute(k_mlp1_bf16, cudaFuncAttributeMaxDynamicSharedMemorySize, (int)SMEM_G);

    cudaStream_t sB;
    cudaStreamCreateWithFlags(&sB, cudaStreamNonBlocking);
    cudaEvent_t evZero, evScan0, evScan1, evHA, evHB, evDone;
    cudaEventCreateWithFlags(&evZero, cudaEventDisableTiming);
    cudaEventCreateWithFlags(&evScan0, cudaEventDisableTiming);
    cudaEventCreateWithFlags(&evScan1, cudaEventDisableTiming);
    cudaEventCreateWithFlags(&evHA, cudaEventDisableTiming);
    cudaEventCreateWithFlags(&evHB, cudaEventDisableTiming);
    cudaEventCreateWithFlags(&evDone, cudaEventDisableTiming);

    int egrid = (EE + 255) / 256;
    int ggrid = (NN * 32 + 255) / 256;
    int tgrid = (NN + 63) / 64;
    int mgrid = (NN + 63) / 64;

    // ---- stream B: wprep first ----
    k_wprep<<<192, 256, 0, sB>>>(W1r0, W1r1, W2r0, W2r1, Wm1, WT);

    // ---- stream 0: zero, then fork ----
    k_zero2<<<(NN + 255) / 256, 256>>>(od0, STATS, syn);
    cudaEventRecord(evZero, 0);
    cudaStreamWaitEvent(sB, evZero, 0);

    // ---- relation-0 setup on stream 0 ----
    k_hist_r<<<egrid, 256>>>(s0, d0, od0, cnt0);
    k_scan_r<<<NBLK, 256>>>(cnt0, od0, bsum, pfx, &syn[0], &syn[1],
                            rp0, cur0, rs_src0, rs_dst0);
    cudaEventRecord(evScan0, 0);
    k_fill_r<<<egrid, 256>>>(s0, d0, cur0, eidx0);

    // ---- relation-1 setup on stream B ----
    k_hist_r<<<egrid, 256, 0, sB>>>(s1, d1, od1, cnt1);
    k_scan_r<<<NBLK, 256, 0, sB>>>(cnt1, od1, bsum + NBLK, pfx + NBLK,
                                   &syn[2], &syn[3], rp1, cur1, rs_src1, rs_dst1);
    cudaEventRecord(evScan1, sB);
    k_fill_r<<<egrid, 256, 0, sB>>>(s1, d1, cur1, eidx1);

    // ---- conv1 relation 0 (stream 0) ----
    k_gather_pk<<<ggrid, 256>>>(xA, eidx0, rp0, rs_src0, rs_dst0, AGG1B, 1);
    cudaStreamWaitEvent(0, evScan1, 0);   // epilogue reads rs_src1
    k_gemm_bf16<<<tgrid, 256, SMEM_G>>>(AGG1B, W1r0T, b1r0, HB, rs_src1, nullptr, 1);
    cudaEventRecord(evHB, 0);

    // ---- conv1 relation 1 (stream B) ----
    k_gather_pk<<<ggrid, 256, 0, sB>>>(xB, eidx1, rp1, rs_src1, rs_dst1, AGG1A, 1);
    cudaStreamWaitEvent(sB, evScan0, 0);  // epilogue reads rs_src0
    k_gemm_bf16<<<tgrid, 256, SMEM_G, sB>>>(AGG1A, W1r1T, b1r1, HA, rs_src0, nullptr, 1);
    cudaEventRecord(evHA, sB);

    // ---- conv2 relation 0 (stream 0, needs HA) -> packed H2B ----
    cudaStreamWaitEvent(0, evHA, 0);
    k_gather_pk<<<ggrid, 256>>>(HA, eidx0, rp0, nullptr, rs_dst0, AGG2B, 0);
    k_gemm_bf16<<<tgrid, 256, SMEM_G>>>(AGG2B, W2r0T, b2r0, nullptr, nullptr, H2Bp, 0);

    // ---- conv2 relation 1 (stream B, needs HB) -> packed H2A ----
    cudaStreamWaitEvent(sB, evHB, 0);
    k_gather_pk<<<ggrid, 256, 0, sB>>>(HB, eidx1, rp1, nullptr, rs_dst1, AGG2A, 0);
    k_gemm_bf16<<<tgrid, 256, SMEM_G, sB>>>(AGG2A, W2r1T, b2r1, nullptr, nullptr, H2Ap, 0);
    cudaEventRecord(evDone, sB);

    // ---- join, MLP head (packed H2 inputs) ----
    cudaStreamWaitEvent(0, evDone, 0);
    k_mlp1_bf16<<<mgrid, 256, SMEM_G>>>(H2Ap, H2Bp, Wm1T, HMLP, STATS, syn,
                                        gamma, beta, BN);
    k_mlp2<<<(NN * 32 + 255) / 256, 256>>>(HMLP, BN, Wm2, out);
}

// round 16
// speedup vs baseline: 1.0244x; 1.0244x over previous
#include <cuda_runtime.h>
#include <cuda_bf16.h>
#include <math.h>

#define NN 50000
#define EE 600000
#define DD 128
#define NF (NN*DD)
#define NBLK 196   // ceil(NN/256)

// ---------------------------------------------------------------------------
__device__ __forceinline__ unsigned packbf(float even, float odd) {
    unsigned d;
    asm("cvt.rn.bf16x2.f32 %0, %1, %2;" : "=r"(d) : "f"(odd), "f"(even));
    return d;
}
__device__ __forceinline__ float bfres(float v) {
    return v - __bfloat162float(__float2bfloat16(v));
}
__device__ __forceinline__ void mma_bf16(
    float& d0, float& d1, float& d2, float& d3,
    unsigned a0, unsigned a1, unsigned a2, unsigned a3,
    unsigned b0, unsigned b1) {
    asm volatile(
        "mma.sync.aligned.m16n8k16.row.col.f32.bf16.bf16.f32 "
        "{%0,%1,%2,%3},{%4,%5,%6,%7},{%8,%9},{%0,%1,%2,%3};"
        : "+f"(d0), "+f"(d1), "+f"(d2), "+f"(d3)
        : "r"(a0), "r"(a1), "r"(a2), "r"(a3), "r"(b0), "r"(b1));
}

// ---------------------------------------------------------------------------
#define OFF_AGG1B 0ULL
#define OFF_AGG1A (1ULL*NF)
#define OFF_AGG2B (2ULL*NF)
#define OFF_AGG2A (3ULL*NF)
#define OFF_HB    (4ULL*NF)
#define OFF_HA    (5ULL*NF)
#define OFF_H2A   (6ULL*NF)   // interleaved packed: uint2{hi,lo} per col-pair
#define OFF_H2B   (7ULL*NF)
#define OFF_HMLP  (8ULL*NF)
#define OFF_RS    (9ULL*NF)
#define OFF_STATS (9ULL*NF + 4ULL*NN)
#define OFF_BN    (OFF_STATS + 256ULL)
#define OFF_WT    (OFF_BN + 256ULL)
#define SCRATCH_FLOATS (OFF_WT + 196608ULL)

__device__ __align__(256) float g_s[SCRATCH_FLOATS];

#define IOFF_EIDX0 0
#define IOFF_EIDX1 (EE)
#define IOFF_OD0   (2*EE)
#define IOFF_CNT0  (2*EE + NN)
#define IOFF_OD1   (2*EE + 2*NN)
#define IOFF_CNT1  (2*EE + 3*NN)
#define IOFF_RP0   (2*EE + 4*NN)
#define IOFF_RP1   (2*EE + 5*NN + 1)
#define IOFF_CUR0  (2*EE + 6*NN + 2)
#define IOFF_CUR1  (2*EE + 7*NN + 2)
#define IOFF_BSUM  (2*EE + 8*NN + 2)
#define IOFF_PFX   (IOFF_BSUM + 2*NBLK)
// syn: [0,1]=rel0 scan, [2,3]=rel1 scan, [4]=mlp1 arrivals
#define IOFF_SYNC  (IOFF_PFX + 2*NBLK)
#define SCRATCH_INTS (IOFF_SYNC + 8)

__device__ __align__(256) int g_i[SCRATCH_INTS];

// ---------------------------------------------------------------------------
__global__ void k_zero2(int* __restrict__ deg, float* __restrict__ stats,
                        int* __restrict__ syn) {
    int i = blockIdx.x * 256 + threadIdx.x;
    if (i < NN) ((int4*)deg)[i] = make_int4(0, 0, 0, 0);
    if (i < 64) ((float4*)stats)[i] = make_float4(0.f, 0.f, 0.f, 0.f);
    if (i < 8) syn[i] = 0;
}

__global__ void k_hist_r(const int* __restrict__ s, const int* __restrict__ d,
                         int* __restrict__ od, int* __restrict__ cnt) {
    int i = blockIdx.x * blockDim.x + threadIdx.x;
    if (i < EE) {
        atomicAdd(&od[s[i]], 1);
        atomicAdd(&cnt[d[i]], 1);
    }
}

__global__ void k_wprep(const float* __restrict__ W1r0, const float* __restrict__ W1r1,
                        const float* __restrict__ W2r0, const float* __restrict__ W2r1,
                        const float* __restrict__ Wm1, unsigned* __restrict__ WT) {
    int idx = blockIdx.x * 256 + threadIdx.x;
    if (idx < 32768) {
        int mat = idx >> 13, r = idx & 8191;
        int n = r >> 6, ku = r & 63;
        int k = 2 * ku;
        const float* Wsrc = (mat == 0) ? W1r0 : (mat == 1) ? W1r1 :
                            (mat == 2) ? W2r0 : W2r1;
        float v0 = __ldg(Wsrc + k * 128 + n);
        float v1 = __ldg(Wsrc + (k + 1) * 128 + n);
        WT[mat * 16384 + n * 64 + ku]        = packbf(v0, v1);
        WT[mat * 16384 + 8192 + n * 64 + ku] = packbf(bfres(v0), bfres(v1));
    } else if (idx < 49152) {
        int r = idx - 32768;
        int n = r >> 7, ku = r & 127;
        int k = 2 * ku;
        float v0 = __ldg(Wm1 + k * 128 + n);
        float v1 = __ldg(Wm1 + (k + 1) * 128 + n);
        WT[65536 + n * 128 + ku]         = packbf(v0, v1);
        WT[65536 + 16384 + n * 128 + ku] = packbf(bfres(v0), bfres(v1));
    }
}

__global__ void __launch_bounds__(256) k_scan_r(
    const int* __restrict__ cnt, const int* __restrict__ od,
    int* __restrict__ bsum, int* __restrict__ pfx,
    int* __restrict__ arr, int* __restrict__ flag,
    int* __restrict__ rp, int* __restrict__ cur,
    float* __restrict__ rs_src, float* __restrict__ rs_dst) {
    __shared__ int sp[256];
    __shared__ int islast;
    int t = threadIdx.x;
    int i = blockIdx.x * 256 + t;
    int v = (i < NN) ? cnt[i] : 0;

    sp[t] = v;
    __syncthreads();
    for (int off = 128; off; off >>= 1) {
        if (t < off) sp[t] += sp[t + off];
        __syncthreads();
    }
    if (t == 0) {
        bsum[blockIdx.x] = sp[0];
        __threadfence();
        int old = atomicAdd(arr, 1);
        islast = (old == NBLK - 1);
    }
    __syncthreads();

    if (islast) {
        int mine = (t < NBLK) ? ((volatile int*)bsum)[t] : 0;
        sp[t] = mine;
        __syncthreads();
        for (int off = 1; off < 256; off <<= 1) {
            int u = (t >= off) ? sp[t - off] : 0;
            __syncthreads();
            sp[t] += u;
            __syncthreads();
        }
        if (t < NBLK) pfx[t] = sp[t] - mine;
        __syncthreads();
        if (t == 0) {
            __threadfence();
            atomicExch(flag, 1);
        }
    }
    if (t == 0) {
        while (((volatile int*)flag)[0] == 0) __nanosleep(64);
    }
    __syncthreads();

    sp[t] = v;
    __syncthreads();
    for (int off = 1; off < 256; off <<= 1) {
        int u = (t >= off) ? sp[t - off] : 0;
        __syncthreads();
        sp[t] += u;
        __syncthreads();
    }
    if (i < NN) {
        int ex = sp[t] - v + ((volatile int*)pfx)[blockIdx.x];
        rp[i] = ex;
        cur[i] = ex;
        rs_src[i] = rsqrtf((float)max(od[i], 1));
        rs_dst[i] = rsqrtf((float)max(v, 1));
    }
    if (i == NN - 1) rp[NN] = EE;
}

__global__ void k_fill_r(const int* __restrict__ s, const int* __restrict__ d,
                         int* __restrict__ cur, int* __restrict__ eidx) {
    int i = blockIdx.x * blockDim.x + threadIdx.x;
    if (i < EE) {
        int p = atomicAdd(&cur[d[i]], 1);
        eidx[p] = s[i];
    }
}

// ---------------------------------------------------------------------------
// gather -> PACKED bf16 hi/lo AGG (R14-exact)
__global__ void __launch_bounds__(256, 8) k_gather_pk(
    const float* __restrict__ x, const int* __restrict__ eidx,
    const int* __restrict__ rowptr, const float* __restrict__ rs_src,
    const float* __restrict__ rs_row, uint4* __restrict__ aggp, int useRs) {
    int g = blockIdx.x * blockDim.x + threadIdx.x;
    int r = g >> 5, lane = g & 31;
    if (r >= NN) return;
    int beg = __ldg(rowptr + r), end = __ldg(rowptr + r + 1);
    float4 acc = make_float4(0.f, 0.f, 0.f, 0.f);
    int e = beg;
    if (useRs) {
        for (; e + 1 < end; e += 2) {
            int sa = __ldg(eidx + e), sb = __ldg(eidx + e + 1);
            float ra = __ldg(rs_src + sa), rb = __ldg(rs_src + sb);
            float4 va = __ldg((const float4*)(x + (long)sa * DD) + lane);
            float4 vb = __ldg((const float4*)(x + (long)sb * DD) + lane);
            acc.x = fmaf(va.x, ra, acc.x); acc.y = fmaf(va.y, ra, acc.y);
            acc.z = fmaf(va.z, ra, acc.z); acc.w = fmaf(va.w, ra, acc.w);
            acc.x = fmaf(vb.x, rb, acc.x); acc.y = fmaf(vb.y, rb, acc.y);
            acc.z = fmaf(vb.z, rb, acc.z); acc.w = fmaf(vb.w, rb, acc.w);
        }
        if (e < end) {
            int sa = __ldg(eidx + e);
            float ra = __ldg(rs_src + sa);
            float4 va = __ldg((const float4*)(x + (long)sa * DD) + lane);
            acc.x = fmaf(va.x, ra, acc.x); acc.y = fmaf(va.y, ra, acc.y);
            acc.z = fmaf(va.z, ra, acc.z); acc.w = fmaf(va.w, ra, acc.w);
        }
    } else {
        for (; e + 1 < end; e += 2) {
            int sa = __ldg(eidx + e), sb = __ldg(eidx + e + 1);
            float4 va = __ldg((const float4*)(x + (long)sa * DD) + lane);
            float4 vb = __ldg((const float4*)(x + (long)sb * DD) + lane);
            acc.x += va.x + vb.x; acc.y += va.y + vb.y;
            acc.z += va.z + vb.z; acc.w += va.w + vb.w;
        }
        if (e < end) {
            int sa = __ldg(eidx + e);
            float4 va = __ldg((const float4*)(x + (long)sa * DD) + lane);
            acc.x += va.x; acc.y += va.y; acc.z += va.z; acc.w += va.w;
        }
    }
    float rd = __ldg(rs_row + r);
    acc.x *= rd; acc.y *= rd; acc.z *= rd; acc.w *= rd;
    unsigned h0 = packbf(acc.x, acc.y), h1 = packbf(acc.z, acc.w);
    unsigned l0 = packbf(bfres(acc.x), bfres(acc.y));
    unsigned l1 = packbf(bfres(acc.z), bfres(acc.w));
    aggp[(long)r * 32 + lane] = make_uint4(h0, h1, l0, l1);
}

// ---------------------------------------------------------------------------
// bf16x3 GEMM on PACKED A. Output: float (out!=null, rso/relu applied) or
// interleaved packed uint2{hi,lo} per col-pair (outp!=null, at [r*64 + c/2]).
#define U_AHI 0
#define U_ALO 4352
#define U_WHI 8704
#define U_WLO 17408
#define SMEM_G ((size_t)26112 * 4)

__global__ void __launch_bounds__(256, 2) k_gemm_bf16(
    const uint4* __restrict__ Xp,
    const unsigned* __restrict__ Wp, const float* __restrict__ bp,
    float* __restrict__ out, const float* __restrict__ rso,
    uint2* __restrict__ outp, int doRelu) {
    extern __shared__ unsigned smu[];
    unsigned* sAhi = smu + U_AHI;
    unsigned* sAlo = smu + U_ALO;
    unsigned* sWhi = smu + U_WHI;
    unsigned* sWlo = smu + U_WLO;

    int tid = threadIdx.x;
    int r0 = blockIdx.x * 64;

    for (int i = tid; i < 2048; i += 256) {
        int row = i >> 5, f4 = i & 31;
        int gr = r0 + row;
        uint4 p = make_uint4(0u, 0u, 0u, 0u);
        if (gr < NN) p = __ldg(Xp + (long)gr * 32 + f4);
        ((uint2*)(sAhi + row * 68))[f4] = make_uint2(p.x, p.y);
        ((uint2*)(sAlo + row * 68))[f4] = make_uint2(p.z, p.w);
    }
    for (int i = tid; i < 4096; i += 256) {
        int n = i >> 5, q = i & 31;
        ((uint2*)(sWhi + n * 68))[q] = __ldg((const uint2*)(Wp + n * 64) + q);
        ((uint2*)(sWlo + n * 68))[q] = __ldg((const uint2*)(Wp + 8192 + n * 64) + q);
    }
    __syncthreads();

    int lane = tid & 31, w = tid >> 5;
    int mg = w >> 2, ng = w & 3;
    int tg = lane & 3, gid = lane >> 2;

    float acc[2][4][4];
#pragma unroll
    for (int mi = 0; mi < 2; mi++)
#pragma unroll
        for (int ni = 0; ni < 4; ni++)
#pragma unroll
            for (int q = 0; q < 4; q++) acc[mi][ni][q] = 0.f;

#pragma unroll
    for (int ks = 0; ks < 8; ks++) {
        unsigned Ah[2][4], Al[2][4], Bh[4][2], Bl[4][2];
#pragma unroll
        for (int mi = 0; mi < 2; mi++) {
            int base = (mg * 32 + mi * 16 + gid) * 68 + ks * 8 + tg;
            Ah[mi][0] = sAhi[base];
            Ah[mi][1] = sAhi[base + 8 * 68];
            Ah[mi][2] = sAhi[base + 4];
            Ah[mi][3] = sAhi[base + 8 * 68 + 4];
            Al[mi][0] = sAlo[base];
            Al[mi][1] = sAlo[base + 8 * 68];
            Al[mi][2] = sAlo[base + 4];
            Al[mi][3] = sAlo[base + 8 * 68 + 4];
        }
#pragma unroll
        for (int ni = 0; ni < 4; ni++) {
            int cb = (ng * 32 + ni * 8 + gid) * 68 + ks * 8 + tg;
            Bh[ni][0] = sWhi[cb];
            Bh[ni][1] = sWhi[cb + 4];
            Bl[ni][0] = sWlo[cb];
            Bl[ni][1] = sWlo[cb + 4];
        }
#pragma unroll
        for (int mi = 0; mi < 2; mi++)
#pragma unroll
            for (int ni = 0; ni < 4; ni++) {
                float* d = acc[mi][ni];
                mma_bf16(d[0], d[1], d[2], d[3],
                         Ah[mi][0], Ah[mi][1], Ah[mi][2], Ah[mi][3],
                         Bh[ni][0], Bh[ni][1]);
                mma_bf16(d[0], d[1], d[2], d[3],
                         Ah[mi][0], Ah[mi][1], Ah[mi][2], Ah[mi][3],
                         Bl[ni][0], Bl[ni][1]);
                mma_bf16(d[0], d[1], d[2], d[3],
                         Al[mi][0], Al[mi][1], Al[mi][2], Al[mi][3],
                         Bh[ni][0], Bh[ni][1]);
            }
    }

#pragma unroll
    for (int ni = 0; ni < 4; ni++) {
        int col = ng * 32 + ni * 8 + 2 * tg;
        float bb0 = __ldg(bp + col), bb1 = __ldg(bp + col + 1);
#pragma unroll
        for (int mi = 0; mi < 2; mi++) {
            int gr = r0 + mg * 32 + mi * 16 + gid;
            if (gr < NN) {
                float v0 = acc[mi][ni][0] + bb0;
                float v1 = acc[mi][ni][1] + bb1;
                if (outp) {
                    outp[(long)gr * 64 + (col >> 1)] = make_uint2(
                        packbf(v0, v1), packbf(bfres(v0), bfres(v1)));
                } else {
                    float ro = rso ? __ldg(rso + gr) : 1.f;
                    if (doRelu) { v0 = fmaxf(v0, 0.f); v1 = fmaxf(v1, 0.f); }
                    *(float2*)(out + (long)gr * DD + col) = make_float2(v0 * ro, v1 * ro);
                }
            }
            int gr8 = gr + 8;
            if (gr8 < NN) {
                float v2 = acc[mi][ni][2] + bb0;
                float v3 = acc[mi][ni][3] + bb1;
                if (outp) {
                    outp[(long)gr8 * 64 + (col >> 1)] = make_uint2(
                        packbf(v2, v3), packbf(bfres(v2), bfres(v3)));
                } else {
                    float ro = rso ? __ldg(rso + gr8) : 1.f;
                    if (doRelu) { v2 = fmaxf(v2, 0.f); v3 = fmaxf(v3, 0.f); }
                    *(float2*)(out + (long)gr8 * DD + col) = make_float2(v2 * ro, v3 * ro);
                }
            }
        }
    }
}

// ---------------------------------------------------------------------------
// MLP layer1 on INTERLEAVED-PACKED H2 inputs + BN stats + BN finalize.
// Xp rows: 32 uint4 each = 2 col-pairs per uint4 (h0,l0,h1,l1).
__global__ void __launch_bounds__(256, 2) k_mlp1_bf16(
    const uint4* __restrict__ XAp, const uint4* __restrict__ XBp,
    const unsigned* __restrict__ WTm1, float* __restrict__ out,
    float* __restrict__ stat, int* __restrict__ syn,
    const float* __restrict__ gamma, const float* __restrict__ beta,
    float* __restrict__ bn) {
    extern __shared__ unsigned smu[];
    unsigned* sAhi = smu + U_AHI;
    unsigned* sAlo = smu + U_ALO;
    unsigned* sWhi = smu + U_WHI;
    unsigned* sWlo = smu + U_WLO;
    int tid = threadIdx.x;
    int r0 = blockIdx.x * 64;
    int lane = tid & 31, w = tid >> 5;
    int mg = w >> 2, ng = w & 3;
    int tg = lane & 3, gid = lane >> 2;

    float acc[2][4][4];
#pragma unroll
    for (int mi = 0; mi < 2; mi++)
#pragma unroll
        for (int ni = 0; ni < 4; ni++)
#pragma unroll
            for (int q = 0; q < 4; q++) acc[mi][ni][q] = 0.f;

    for (int ph = 0; ph < 2; ph++) {
        const uint4* Xp = ph ? XBp : XAp;
        for (int i = tid; i < 2048; i += 256) {
            int row = i >> 5, f4 = i & 31;
            int gr = r0 + row;
            uint4 p = make_uint4(0u, 0u, 0u, 0u);
            if (gr < NN) p = __ldg(Xp + (long)gr * 32 + f4);
            // p = (h_pair0, l_pair0, h_pair1, l_pair1)
            ((uint2*)(sAhi + row * 68))[f4] = make_uint2(p.x, p.z);
            ((uint2*)(sAlo + row * 68))[f4] = make_uint2(p.y, p.w);
        }
        for (int i = tid; i < 4096; i += 256) {
            int n = i >> 5, q = i & 31;
            ((uint2*)(sWhi + n * 68))[q] =
                __ldg((const uint2*)(WTm1 + n * 128 + ph * 64) + q);
            ((uint2*)(sWlo + n * 68))[q] =
                __ldg((const uint2*)(WTm1 + 16384 + n * 128 + ph * 64) + q);
        }
        __syncthreads();

#pragma unroll
        for (int ks = 0; ks < 8; ks++) {
            unsigned Ah[2][4], Al[2][4], Bh[4][2], Bl[4][2];
#pragma unroll
            for (int mi = 0; mi < 2; mi++) {
                int base = (mg * 32 + mi * 16 + gid) * 68 + ks * 8 + tg;
                Ah[mi][0] = sAhi[base];
                Ah[mi][1] = sAhi[base + 8 * 68];
                Ah[mi][2] = sAhi[base + 4];
                Ah[mi][3] = sAhi[base + 8 * 68 + 4];
                Al[mi][0] = sAlo[base];
                Al[mi][1] = sAlo[base + 8 * 68];
                Al[mi][2] = sAlo[base + 4];
                Al[mi][3] = sAlo[base + 8 * 68 + 4];
            }
#pragma unroll
            for (int ni = 0; ni < 4; ni++) {
                int cb = (ng * 32 + ni * 8 + gid) * 68 + ks * 8 + tg;
                Bh[ni][0] = sWhi[cb];
                Bh[ni][1] = sWhi[cb + 4];
                Bl[ni][0] = sWlo[cb];
                Bl[ni][1] = sWlo[cb + 4];
            }
#pragma unroll
            for (int mi = 0; mi < 2; mi++)
#pragma unroll
                for (int ni = 0; ni < 4; ni++) {
                    float* d = acc[mi][ni];
                    mma_bf16(d[0], d[1], d[2], d[3],
                             Ah[mi][0], Ah[mi][1], Ah[mi][2], Ah[mi][3],
                             Bh[ni][0], Bh[ni][1]);
                    mma_bf16(d[0], d[1], d[2], d[3],
                             Ah[mi][0], Ah[mi][1], Ah[mi][2], Ah[mi][3],
                             Bl[ni][0], Bl[ni][1]);
                    mma_bf16(d[0], d[1], d[2], d[3],
                             Al[mi][0], Al[mi][1], Al[mi][2], Al[mi][3],
                             Bh[ni][0], Bh[ni][1]);
                }
        }
        __syncthreads();
    }

    float cs[4][2], cq[4][2];
#pragma unroll
    for (int ni = 0; ni < 4; ni++) {
        cs[ni][0] = cs[ni][1] = 0.f;
        cq[ni][0] = cq[ni][1] = 0.f;
    }
#pragma unroll
    for (int ni = 0; ni < 4; ni++) {
        int col = ng * 32 + ni * 8 + 2 * tg;
#pragma unroll
        for (int mi = 0; mi < 2; mi++) {
            int gr = r0 + mg * 32 + mi * 16 + gid;
            if (gr < NN) {
                float v0 = acc[mi][ni][0], v1 = acc[mi][ni][1];
                *(float2*)(out + (long)gr * DD + col) = make_float2(v0, v1);
                cs[ni][0] += v0; cq[ni][0] += v0 * v0;
                cs[ni][1] += v1; cq[ni][1] += v1 * v1;
            }
            int gr8 = gr + 8;
            if (gr8 < NN) {
                float v2 = acc[mi][ni][2], v3 = acc[mi][ni][3];
                *(float2*)(out + (long)gr8 * DD + col) = make_float2(v2, v3);
                cs[ni][0] += v2; cq[ni][0] += v2 * v2;
                cs[ni][1] += v3; cq[ni][1] += v3 * v3;
            }
        }
    }
    __syncthreads();
    float* ssum = (float*)smu;
    float* ssq  = (float*)smu + 128;
    if (tid < 256) ((float*)smu)[tid] = 0.f;
    __syncthreads();
#pragma unroll
    for (int ni = 0; ni < 4; ni++) {
        int col = ng * 32 + ni * 8 + 2 * tg;
        atomicAdd(&ssum[col], cs[ni][0]);
        atomicAdd(&ssum[col + 1], cs[ni][1]);
        atomicAdd(&ssq[col], cq[ni][0]);
        atomicAdd(&ssq[col + 1], cq[ni][1]);
    }
    __syncthreads();
    if (tid < 128) {
        atomicAdd(&stat[tid], ssum[tid]);
        atomicAdd(&stat[128 + tid], ssq[tid]);
    }

    __shared__ int lastblk;
    __threadfence();
    __syncthreads();
    if (tid == 0) {
        int old = atomicAdd(&syn[4], 1);
        lastblk = (old == (int)gridDim.x - 1);
    }
    __syncthreads();
    if (lastblk && tid < 128) {
        float s  = atomicAdd(&stat[tid], 0.f);
        float sq = atomicAdd(&stat[128 + tid], 0.f);
        float mu  = s * (1.f / NN);
        float var = sq * (1.f / NN) - mu * mu;
        float sc  = __ldg(gamma + tid) * rsqrtf(var + 1e-5f);
        bn[tid]       = sc;
        bn[128 + tid] = __ldg(beta + tid) - mu * sc;
    }
}

// ---------------------------------------------------------------------------
__global__ void __launch_bounds__(256) k_mlp2(
    const float* __restrict__ H, const float* __restrict__ bn,
    const float* __restrict__ Wm2, float* __restrict__ out) {
    __shared__ float sw[256];
    __shared__ float sb[256];
    int tid = threadIdx.x;
    if (tid < 256) { sw[tid] = Wm2[tid]; sb[tid] = bn[tid]; }
    __syncthreads();
    int g = blockIdx.x * blockDim.x + tid;
    int row = g >> 5, lane = g & 31;
    if (row >= NN) return;
    float4 h = ((const float4*)(H + (long)row * DD))[lane];
    float s0 = 0.f, s1 = 0.f;
    int c = lane * 4;
    float hv[4] = {h.x, h.y, h.z, h.w};
#pragma unroll
    for (int j = 0; j < 4; j++) {
        int cc = c + j;
        float v = fmaxf(hv[j] * sb[cc] + sb[128 + cc], 0.f);
        s0 += v * sw[cc * 2];
        s1 += v * sw[cc * 2 + 1];
    }
#pragma unroll
    for (int off = 16; off > 0; off >>= 1) {
        s0 += __shfl_down_sync(0xffffffffu, s0, off);
        s1 += __shfl_down_sync(0xffffffffu, s1, off);
    }
    if (lane == 0) {
        out[row * 2]     = s0;
        out[row * 2 + 1] = s1;
    }
}

// ---------------------------------------------------------------------------
extern "C" void kernel_launch(void* const* d_in, const int* in_sizes, int n_in,
                              void* d_out, int out_size) {
    const float* xA    = (const float*)d_in[0];
    const float* xB    = (const float*)d_in[1];
    const int*   s0    = (const int*)d_in[2];
    const int*   d0    = (const int*)d_in[3];
    const int*   s1    = (const int*)d_in[4];
    const int*   d1    = (const int*)d_in[5];
    const float* W1r0  = (const float*)d_in[6];
    const float* b1r0  = (const float*)d_in[7];
    const float* W1r1  = (const float*)d_in[8];
    const float* b1r1  = (const float*)d_in[9];
    const float* W2r0  = (const float*)d_in[10];
    const float* b2r0  = (const float*)d_in[11];
    const float* W2r1  = (const float*)d_in[12];
    const float* b2r1  = (const float*)d_in[13];
    const float* Wm1   = (const float*)d_in[14];
    const float* gamma = (const float*)d_in[15];
    const float* beta  = (const float*)d_in[16];
    const float* Wm2   = (const float*)d_in[17];
    float* out = (float*)d_out;

    float* S = nullptr;
    cudaGetSymbolAddress((void**)&S, g_s);
    int* I = nullptr;
    cudaGetSymbolAddress((void**)&I, g_i);

    uint4* AGG1B = (uint4*)(S + OFF_AGG1B);
    uint4* AGG1A = (uint4*)(S + OFF_AGG1A);
    uint4* AGG2B = (uint4*)(S + OFF_AGG2B);
    uint4* AGG2A = (uint4*)(S + OFF_AGG2A);
    float* HB    = S + OFF_HB;
    float* HA    = S + OFF_HA;
    uint2* H2Ap  = (uint2*)(S + OFF_H2A);   // interleaved packed
    uint2* H2Bp  = (uint2*)(S + OFF_H2B);
    float* HMLP  = S + OFF_HMLP;
    float* RS    = S + OFF_RS;
    float* STATS = S + OFF_STATS;
    float* BN    = S + OFF_BN;
    unsigned* WT = (unsigned*)(S + OFF_WT);

    int* eidx0 = I + IOFF_EIDX0;
    int* eidx1 = I + IOFF_EIDX1;
    int* od0   = I + IOFF_OD0;
    int* cnt0  = I + IOFF_CNT0;
    int* od1   = I + IOFF_OD1;
    int* cnt1  = I + IOFF_CNT1;
    int* rp0   = I + IOFF_RP0;
    int* rp1   = I + IOFF_RP1;
    int* cur0  = I + IOFF_CUR0;
    int* cur1  = I + IOFF_CUR1;
    int* bsum  = I + IOFF_BSUM;
    int* pfx   = I + IOFF_PFX;
    int* syn   = I + IOFF_SYNC;

    float* rs_src0 = RS + 0 * NN;
    float* rs_dst0 = RS + 1 * NN;
    float* rs_src1 = RS + 2 * NN;
    float* rs_dst1 = RS + 3 * NN;

    unsigned* W1r0T = WT + 0;
    unsigned* W1r1T = WT + 16384;
    unsigned* W2r0T = WT + 32768;
    unsigned* W2r1T = WT + 49152;
    unsigned* Wm1T  = WT + 65536;

    cudaFuncSetAttribute(k_gemm_bf16, cudaFuncAttributeMaxDynamicSharedMemorySize, (int)SMEM_G);
    cudaFuncSetAttribute(k_mlp1_bf16, cudaFuncAttributeMaxDynamicSharedMemorySize, (int)SMEM_G);

    cudaStream_t sB;
    cudaStreamCreateWithFlags(&sB, cudaStreamNonBlocking);
    cudaEvent_t evZero, evScan0, evScan1, evHA, evHB, evDone;
    cudaEventCreateWithFlags(&evZero, cudaEventDisableTiming);
    cudaEventCreateWithFlags(&evScan0, cudaEventDisableTiming);
    cudaEventCreateWithFlags(&evScan1, cudaEventDisableTiming);
    cudaEventCreateWithFlags(&evHA, cudaEventDisableTiming);
    cudaEventCreateWithFlags(&evHB, cudaEventDisableTiming);
    cudaEventCreateWithFlags(&evDone, cudaEventDisableTiming);

    int egrid = (EE + 255) / 256;
    int ggrid = (NN * 32 + 255) / 256;
    int tgrid = (NN + 63) / 64;
    int mgrid = (NN + 63) / 64;

    // ---- stream B: wprep first ----
    k_wprep<<<192, 256, 0, sB>>>(W1r0, W1r1, W2r0, W2r1, Wm1, WT);

    // ---- stream 0: zero, then fork ----
    k_zero2<<<(NN + 255) / 256, 256>>>(od0, STATS, syn);
    cudaEventRecord(evZero, 0);
    cudaStreamWaitEvent(sB, evZero, 0);

    // ---- relation-0 setup on stream 0 ----
    k_hist_r<<<egrid, 256>>>(s0, d0, od0, cnt0);
    k_scan_r<<<NBLK, 256>>>(cnt0, od0, bsum, pfx, &syn[0], &syn[1],
                            rp0, cur0, rs_src0, rs_dst0);
    cudaEventRecord(evScan0, 0);
    k_fill_r<<<egrid, 256>>>(s0, d0, cur0, eidx0);

    // ---- relation-1 setup on stream B ----
    k_hist_r<<<egrid, 256, 0, sB>>>(s1, d1, od1, cnt1);
    k_scan_r<<<NBLK, 256, 0, sB>>>(cnt1, od1, bsum + NBLK, pfx + NBLK,
                                   &syn[2], &syn[3], rp1, cur1, rs_src1, rs_dst1);
    cudaEventRecord(evScan1, sB);
    k_fill_r<<<egrid, 256, 0, sB>>>(s1, d1, cur1, eidx1);

    // ---- conv1 relation 0 (stream 0) ----
    k_gather_pk<<<ggrid, 256>>>(xA, eidx0, rp0, rs_src0, rs_dst0, AGG1B, 1);
    cudaStreamWaitEvent(0, evScan1, 0);   // epilogue reads rs_src1
    k_gemm_bf16<<<tgrid, 256, SMEM_G>>>(AGG1B, W1r0T, b1r0, HB, rs_src1, nullptr, 1);
    cudaEventRecord(evHB, 0);

    // ---- conv1 relation 1 (stream B) ----
    k_gather_pk<<<ggrid, 256, 0, sB>>>(xB, eidx1, rp1, rs_src1, rs_dst1, AGG1A, 1);
    cudaStreamWaitEvent(sB, evScan0, 0);  // epilogue reads rs_src0
    k_gemm_bf16<<<tgrid, 256, SMEM_G, sB>>>(AGG1A, W1r1T, b1r1, HA, rs_src0, nullptr, 1);
    cudaEventRecord(evHA, sB);

    // ---- conv2 relation 0 (stream 0, needs HA) -> packed H2B ----
    cudaStreamWaitEvent(0, evHA, 0);
    k_gather_pk<<<ggrid, 256>>>(HA, eidx0, rp0, nullptr, rs_dst0, AGG2B, 0);
    k_gemm_bf16<<<tgrid, 256, SMEM_G>>>(AGG2B, W2r0T, b2r0, nullptr, nullptr, H2Bp, 0);

    // ---- conv2 relation 1 (stream B, needs HB) -> packed H2A ----
    cudaStreamWaitEvent(sB, evHB, 0);
    k_gather_pk<<<ggrid, 256, 0, sB>>>(HB, eidx1, rp1, nullptr, rs_dst1, AGG2A, 0);
    k_gemm_bf16<<<tgrid, 256, SMEM_G, sB>>>(AGG2A, W2r1T, b2r1, nullptr, nullptr, H2Ap, 0);
    cudaEventRecord(evDone, sB);

    // ---- join, MLP head (interleaved-packed H2 inputs) ----
    cudaStreamWaitEvent(0, evDone, 0);
    k_mlp1_bf16<<<mgrid, 256, SMEM_G>>>((const uint4*)H2Ap, (const uint4*)H2Bp,
                                        Wm1T, HMLP, STATS, syn, gamma, beta, BN);
    k_mlp2<<<(NN * 32 + 255) / 256, 256>>>(HMLP, BN, Wm2, out);
}

// round 17
// speedup vs baseline: 1.0840x; 1.0581x over previous
#include <cuda_runtime.h>
#include <cuda_bf16.h>
#include <math.h>

#define NN 50000
#define EE 600000
#define DD 128
#define NF (NN*DD)
#define NBLK 196   // ceil(NN/256)

// ---------------------------------------------------------------------------
__device__ __forceinline__ unsigned packbf(float even, float odd) {
    unsigned d;
    asm("cvt.rn.bf16x2.f32 %0, %1, %2;" : "=r"(d) : "f"(odd), "f"(even));
    return d;
}
__device__ __forceinline__ float bfres(float v) {
    return v - __bfloat162float(__float2bfloat16(v));
}
__device__ __forceinline__ void mma_bf16(
    float& d0, float& d1, float& d2, float& d3,
    unsigned a0, unsigned a1, unsigned a2, unsigned a3,
    unsigned b0, unsigned b1) {
    asm volatile(
        "mma.sync.aligned.m16n8k16.row.col.f32.bf16.bf16.f32 "
        "{%0,%1,%2,%3},{%4,%5,%6,%7},{%8,%9},{%0,%1,%2,%3};"
        : "+f"(d0), "+f"(d1), "+f"(d2), "+f"(d3)
        : "r"(a0), "r"(a1), "r"(a2), "r"(a3), "r"(b0), "r"(b1));
}

// ---------------------------------------------------------------------------
#define OFF_AGG1B 0ULL
#define OFF_AGG1A (1ULL*NF)
#define OFF_AGG2B (2ULL*NF)
#define OFF_AGG2A (3ULL*NF)
#define OFF_HB    (4ULL*NF)
#define OFF_HA    (5ULL*NF)
#define OFF_H2A   (6ULL*NF)
#define OFF_H2B   (7ULL*NF)
#define OFF_HMLP  (8ULL*NF)
#define OFF_RS    (9ULL*NF)
#define OFF_STATS (9ULL*NF + 4ULL*NN)
#define OFF_BN    (OFF_STATS + 256ULL)
#define OFF_WT    (OFF_BN + 256ULL)
#define SCRATCH_FLOATS (OFF_WT + 196608ULL)

__device__ __align__(256) float g_s[SCRATCH_FLOATS];

#define IOFF_EIDX0 0
#define IOFF_EIDX1 (EE)
#define IOFF_OD0   (2*EE)
#define IOFF_CNT0  (2*EE + NN)
#define IOFF_OD1   (2*EE + 2*NN)
#define IOFF_CNT1  (2*EE + 3*NN)
#define IOFF_RP0   (2*EE + 4*NN)
#define IOFF_RP1   (2*EE + 5*NN + 1)
#define IOFF_CUR0  (2*EE + 6*NN + 2)
#define IOFF_CUR1  (2*EE + 7*NN + 2)
#define IOFF_BSUM  (2*EE + 8*NN + 2)
#define IOFF_PFX   (IOFF_BSUM + 2*NBLK)
// syn: [0,1]=rel0 scan, [2,3]=rel1 scan, [4]=mlp1 arrivals
#define IOFF_SYNC  (IOFF_PFX + 2*NBLK)
#define SCRATCH_INTS (IOFF_SYNC + 8)

__device__ __align__(256) int g_i[SCRATCH_INTS];

// ---------------------------------------------------------------------------
__global__ void k_zero2(int* __restrict__ deg, float* __restrict__ stats,
                        int* __restrict__ syn) {
    int i = blockIdx.x * 256 + threadIdx.x;
    if (i < NN) ((int4*)deg)[i] = make_int4(0, 0, 0, 0);
    if (i < 64) ((float4*)stats)[i] = make_float4(0.f, 0.f, 0.f, 0.f);
    if (i < 8) syn[i] = 0;
}

__global__ void k_hist_r(const int* __restrict__ s, const int* __restrict__ d,
                         int* __restrict__ od, int* __restrict__ cnt) {
    int i = blockIdx.x * blockDim.x + threadIdx.x;
    if (i < EE) {
        atomicAdd(&od[s[i]], 1);
        atomicAdd(&cnt[d[i]], 1);
    }
}

__global__ void k_wprep(const float* __restrict__ W1r0, const float* __restrict__ W1r1,
                        const float* __restrict__ W2r0, const float* __restrict__ W2r1,
                        const float* __restrict__ Wm1, unsigned* __restrict__ WT) {
    int idx = blockIdx.x * 256 + threadIdx.x;
    if (idx < 32768) {
        int mat = idx >> 13, r = idx & 8191;
        int n = r >> 6, ku = r & 63;
        int k = 2 * ku;
        const float* Wsrc = (mat == 0) ? W1r0 : (mat == 1) ? W1r1 :
                            (mat == 2) ? W2r0 : W2r1;
        float v0 = __ldg(Wsrc + k * 128 + n);
        float v1 = __ldg(Wsrc + (k + 1) * 128 + n);
        WT[mat * 16384 + n * 64 + ku]        = packbf(v0, v1);
        WT[mat * 16384 + 8192 + n * 64 + ku] = packbf(bfres(v0), bfres(v1));
    } else if (idx < 49152) {
        int r = idx - 32768;
        int n = r >> 7, ku = r & 127;
        int k = 2 * ku;
        float v0 = __ldg(Wm1 + k * 128 + n);
        float v1 = __ldg(Wm1 + (k + 1) * 128 + n);
        WT[65536 + n * 128 + ku]         = packbf(v0, v1);
        WT[65536 + 16384 + n * 128 + ku] = packbf(bfres(v0), bfres(v1));
    }
}

__global__ void __launch_bounds__(256) k_scan_r(
    const int* __restrict__ cnt, const int* __restrict__ od,
    int* __restrict__ bsum, int* __restrict__ pfx,
    int* __restrict__ arr, int* __restrict__ flag,
    int* __restrict__ rp, int* __restrict__ cur,
    float* __restrict__ rs_src, float* __restrict__ rs_dst) {
    __shared__ int sp[256];
    __shared__ int islast;
    int t = threadIdx.x;
    int i = blockIdx.x * 256 + t;
    int v = (i < NN) ? cnt[i] : 0;

    sp[t] = v;
    __syncthreads();
    for (int off = 128; off; off >>= 1) {
        if (t < off) sp[t] += sp[t + off];
        __syncthreads();
    }
    if (t == 0) {
        bsum[blockIdx.x] = sp[0];
        __threadfence();
        int old = atomicAdd(arr, 1);
        islast = (old == NBLK - 1);
    }
    __syncthreads();

    if (islast) {
        int mine = (t < NBLK) ? ((volatile int*)bsum)[t] : 0;
        sp[t] = mine;
        __syncthreads();
        for (int off = 1; off < 256; off <<= 1) {
            int u = (t >= off) ? sp[t - off] : 0;
            __syncthreads();
            sp[t] += u;
            __syncthreads();
        }
        if (t < NBLK) pfx[t] = sp[t] - mine;
        __syncthreads();
        if (t == 0) {
            __threadfence();
            atomicExch(flag, 1);
        }
    }
    if (t == 0) {
        while (((volatile int*)flag)[0] == 0) __nanosleep(64);
    }
    __syncthreads();

    sp[t] = v;
    __syncthreads();
    for (int off = 1; off < 256; off <<= 1) {
        int u = (t >= off) ? sp[t - off] : 0;
        __syncthreads();
        sp[t] += u;
        __syncthreads();
    }
    if (i < NN) {
        int ex = sp[t] - v + ((volatile int*)pfx)[blockIdx.x];
        rp[i] = ex;
        cur[i] = ex;
        rs_src[i] = rsqrtf((float)max(od[i], 1));
        rs_dst[i] = rsqrtf((float)max(v, 1));
    }
    if (i == NN - 1) rp[NN] = EE;
}

__global__ void k_fill_r(const int* __restrict__ s, const int* __restrict__ d,
                         int* __restrict__ cur, int* __restrict__ eidx) {
    int i = blockIdx.x * blockDim.x + threadIdx.x;
    if (i < EE) {
        int p = atomicAdd(&cur[d[i]], 1);
        eidx[p] = s[i];
    }
}

// ---------------------------------------------------------------------------
// gather -> PACKED bf16 hi/lo AGG (R14-exact)
__global__ void __launch_bounds__(256, 8) k_gather_pk(
    const float* __restrict__ x, const int* __restrict__ eidx,
    const int* __restrict__ rowptr, const float* __restrict__ rs_src,
    const float* __restrict__ rs_row, uint4* __restrict__ aggp, int useRs) {
    int g = blockIdx.x * blockDim.x + threadIdx.x;
    int r = g >> 5, lane = g & 31;
    if (r >= NN) return;
    int beg = __ldg(rowptr + r), end = __ldg(rowptr + r + 1);
    float4 acc = make_float4(0.f, 0.f, 0.f, 0.f);
    int e = beg;
    if (useRs) {
        for (; e + 1 < end; e += 2) {
            int sa = __ldg(eidx + e), sb = __ldg(eidx + e + 1);
            float ra = __ldg(rs_src + sa), rb = __ldg(rs_src + sb);
            float4 va = __ldg((const float4*)(x + (long)sa * DD) + lane);
            float4 vb = __ldg((const float4*)(x + (long)sb * DD) + lane);
            acc.x = fmaf(va.x, ra, acc.x); acc.y = fmaf(va.y, ra, acc.y);
            acc.z = fmaf(va.z, ra, acc.z); acc.w = fmaf(va.w, ra, acc.w);
            acc.x = fmaf(vb.x, rb, acc.x); acc.y = fmaf(vb.y, rb, acc.y);
            acc.z = fmaf(vb.z, rb, acc.z); acc.w = fmaf(vb.w, rb, acc.w);
        }
        if (e < end) {
            int sa = __ldg(eidx + e);
            float ra = __ldg(rs_src + sa);
            float4 va = __ldg((const float4*)(x + (long)sa * DD) + lane);
            acc.x = fmaf(va.x, ra, acc.x); acc.y = fmaf(va.y, ra, acc.y);
            acc.z = fmaf(va.z, ra, acc.z); acc.w = fmaf(va.w, ra, acc.w);
        }
    } else {
        for (; e + 1 < end; e += 2) {
            int sa = __ldg(eidx + e), sb = __ldg(eidx + e + 1);
            float4 va = __ldg((const float4*)(x + (long)sa * DD) + lane);
            float4 vb = __ldg((const float4*)(x + (long)sb * DD) + lane);
            acc.x += va.x + vb.x; acc.y += va.y + vb.y;
            acc.z += va.z + vb.z; acc.w += va.w + vb.w;
        }
        if (e < end) {
            int sa = __ldg(eidx + e);
            float4 va = __ldg((const float4*)(x + (long)sa * DD) + lane);
            acc.x += va.x; acc.y += va.y; acc.z += va.z; acc.w += va.w;
        }
    }
    float rd = __ldg(rs_row + r);
    acc.x *= rd; acc.y *= rd; acc.z *= rd; acc.w *= rd;
    unsigned h0 = packbf(acc.x, acc.y), h1 = packbf(acc.z, acc.w);
    unsigned l0 = packbf(bfres(acc.x), bfres(acc.y));
    unsigned l1 = packbf(bfres(acc.z), bfres(acc.w));
    aggp[(long)r * 32 + lane] = make_uint4(h0, h1, l0, l1);
}

// ---------------------------------------------------------------------------
// bf16x3 GEMM on PACKED A (R14-exact; fp32 output, optional rso/relu)
#define U_AHI 0
#define U_ALO 4352
#define U_WHI 8704
#define U_WLO 17408
#define SMEM_G ((size_t)26112 * 4)

__global__ void __launch_bounds__(256, 2) k_gemm_bf16(
    const uint4* __restrict__ Xp,
    const unsigned* __restrict__ Wp, const float* __restrict__ bp,
    float* __restrict__ out, const float* __restrict__ rso,
    int doRelu) {
    extern __shared__ unsigned smu[];
    unsigned* sAhi = smu + U_AHI;
    unsigned* sAlo = smu + U_ALO;
    unsigned* sWhi = smu + U_WHI;
    unsigned* sWlo = smu + U_WLO;

    int tid = threadIdx.x;
    int r0 = blockIdx.x * 64;

    for (int i = tid; i < 2048; i += 256) {
        int row = i >> 5, f4 = i & 31;
        int gr = r0 + row;
        uint4 p = make_uint4(0u, 0u, 0u, 0u);
        if (gr < NN) p = __ldg(Xp + (long)gr * 32 + f4);
        ((uint2*)(sAhi + row * 68))[f4] = make_uint2(p.x, p.y);
        ((uint2*)(sAlo + row * 68))[f4] = make_uint2(p.z, p.w);
    }
    for (int i = tid; i < 4096; i += 256) {
        int n = i >> 5, q = i & 31;
        ((uint2*)(sWhi + n * 68))[q] = __ldg((const uint2*)(Wp + n * 64) + q);
        ((uint2*)(sWlo + n * 68))[q] = __ldg((const uint2*)(Wp + 8192 + n * 64) + q);
    }
    __syncthreads();

    int lane = tid & 31, w = tid >> 5;
    int mg = w >> 2, ng = w & 3;
    int tg = lane & 3, gid = lane >> 2;

    float acc[2][4][4];
#pragma unroll
    for (int mi = 0; mi < 2; mi++)
#pragma unroll
        for (int ni = 0; ni < 4; ni++)
#pragma unroll
            for (int q = 0; q < 4; q++) acc[mi][ni][q] = 0.f;

#pragma unroll
    for (int ks = 0; ks < 8; ks++) {
        unsigned Ah[2][4], Al[2][4], Bh[4][2], Bl[4][2];
#pragma unroll
        for (int mi = 0; mi < 2; mi++) {
            int base = (mg * 32 + mi * 16 + gid) * 68 + ks * 8 + tg;
            Ah[mi][0] = sAhi[base];
            Ah[mi][1] = sAhi[base + 8 * 68];
            Ah[mi][2] = sAhi[base + 4];
            Ah[mi][3] = sAhi[base + 8 * 68 + 4];
            Al[mi][0] = sAlo[base];
            Al[mi][1] = sAlo[base + 8 * 68];
            Al[mi][2] = sAlo[base + 4];
            Al[mi][3] = sAlo[base + 8 * 68 + 4];
        }
#pragma unroll
        for (int ni = 0; ni < 4; ni++) {
            int cb = (ng * 32 + ni * 8 + gid) * 68 + ks * 8 + tg;
            Bh[ni][0] = sWhi[cb];
            Bh[ni][1] = sWhi[cb + 4];
            Bl[ni][0] = sWlo[cb];
            Bl[ni][1] = sWlo[cb + 4];
        }
#pragma unroll
        for (int mi = 0; mi < 2; mi++)
#pragma unroll
            for (int ni = 0; ni < 4; ni++) {
                float* d = acc[mi][ni];
                mma_bf16(d[0], d[1], d[2], d[3],
                         Ah[mi][0], Ah[mi][1], Ah[mi][2], Ah[mi][3],
                         Bh[ni][0], Bh[ni][1]);
                mma_bf16(d[0], d[1], d[2], d[3],
                         Ah[mi][0], Ah[mi][1], Ah[mi][2], Ah[mi][3],
                         Bl[ni][0], Bl[ni][1]);
                mma_bf16(d[0], d[1], d[2], d[3],
                         Al[mi][0], Al[mi][1], Al[mi][2], Al[mi][3],
                         Bh[ni][0], Bh[ni][1]);
            }
    }

#pragma unroll
    for (int ni = 0; ni < 4; ni++) {
        int col = ng * 32 + ni * 8 + 2 * tg;
        float bb0 = __ldg(bp + col), bb1 = __ldg(bp + col + 1);
#pragma unroll
        for (int mi = 0; mi < 2; mi++) {
            int gr = r0 + mg * 32 + mi * 16 + gid;
            if (gr < NN) {
                float v0 = acc[mi][ni][0] + bb0;
                float v1 = acc[mi][ni][1] + bb1;
                float ro = rso ? __ldg(rso + gr) : 1.f;
                if (doRelu) { v0 = fmaxf(v0, 0.f); v1 = fmaxf(v1, 0.f); }
                *(float2*)(out + (long)gr * DD + col) = make_float2(v0 * ro, v1 * ro);
            }
            int gr8 = gr + 8;
            if (gr8 < NN) {
                float v2 = acc[mi][ni][2] + bb0;
                float v3 = acc[mi][ni][3] + bb1;
                float ro = rso ? __ldg(rso + gr8) : 1.f;
                if (doRelu) { v2 = fmaxf(v2, 0.f); v3 = fmaxf(v3, 0.f); }
                *(float2*)(out + (long)gr8 * DD + col) = make_float2(v2 * ro, v3 * ro);
            }
        }
    }
}

// ---------------------------------------------------------------------------
// MLP layer1 (fp32 H2 inputs, R14-exact) + BN stats + last-block BN finalize
__global__ void __launch_bounds__(256, 2) k_mlp1_bf16(
    const float* __restrict__ XA, const float* __restrict__ XB,
    const unsigned* __restrict__ WTm1, float* __restrict__ out,
    float* __restrict__ stat, int* __restrict__ syn,
    const float* __restrict__ gamma, const float* __restrict__ beta,
    float* __restrict__ bn) {
    extern __shared__ unsigned smu[];
    unsigned* sAhi = smu + U_AHI;
    unsigned* sAlo = smu + U_ALO;
    unsigned* sWhi = smu + U_WHI;
    unsigned* sWlo = smu + U_WLO;
    int tid = threadIdx.x;
    int r0 = blockIdx.x * 64;
    int lane = tid & 31, w = tid >> 5;
    int mg = w >> 2, ng = w & 3;
    int tg = lane & 3, gid = lane >> 2;

    float acc[2][4][4];
#pragma unroll
    for (int mi = 0; mi < 2; mi++)
#pragma unroll
        for (int ni = 0; ni < 4; ni++)
#pragma unroll
            for (int q = 0; q < 4; q++) acc[mi][ni][q] = 0.f;

    for (int ph = 0; ph < 2; ph++) {
        const float* X = ph ? XB : XA;
        for (int i = tid; i < 2048; i += 256) {
            int row = i >> 5, f4 = i & 31;
            int gr = r0 + row;
            float4 v = make_float4(0.f, 0.f, 0.f, 0.f);
            if (gr < NN) v = __ldg((const float4*)(X + (long)gr * DD) + f4);
            ((uint2*)(sAhi + row * 68))[f4] = make_uint2(packbf(v.x, v.y), packbf(v.z, v.w));
            ((uint2*)(sAlo + row * 68))[f4] = make_uint2(
                packbf(bfres(v.x), bfres(v.y)), packbf(bfres(v.z), bfres(v.w)));
        }
        for (int i = tid; i < 4096; i += 256) {
            int n = i >> 5, q = i & 31;
            ((uint2*)(sWhi + n * 68))[q] =
                __ldg((const uint2*)(WTm1 + n * 128 + ph * 64) + q);
            ((uint2*)(sWlo + n * 68))[q] =
                __ldg((const uint2*)(WTm1 + 16384 + n * 128 + ph * 64) + q);
        }
        __syncthreads();

#pragma unroll
        for (int ks = 0; ks < 8; ks++) {
            unsigned Ah[2][4], Al[2][4], Bh[4][2], Bl[4][2];
#pragma unroll
            for (int mi = 0; mi < 2; mi++) {
                int base = (mg * 32 + mi * 16 + gid) * 68 + ks * 8 + tg;
                Ah[mi][0] = sAhi[base];
                Ah[mi][1] = sAhi[base + 8 * 68];
                Ah[mi][2] = sAhi[base + 4];
                Ah[mi][3] = sAhi[base + 8 * 68 + 4];
                Al[mi][0] = sAlo[base];
                Al[mi][1] = sAlo[base + 8 * 68];
                Al[mi][2] = sAlo[base + 4];
                Al[mi][3] = sAlo[base + 8 * 68 + 4];
            }
#pragma unroll
            for (int ni = 0; ni < 4; ni++) {
                int cb = (ng * 32 + ni * 8 + gid) * 68 + ks * 8 + tg;
                Bh[ni][0] = sWhi[cb];
                Bh[ni][1] = sWhi[cb + 4];
                Bl[ni][0] = sWlo[cb];
                Bl[ni][1] = sWlo[cb + 4];
            }
#pragma unroll
            for (int mi = 0; mi < 2; mi++)
#pragma unroll
                for (int ni = 0; ni < 4; ni++) {
                    float* d = acc[mi][ni];
                    mma_bf16(d[0], d[1], d[2], d[3],
                             Ah[mi][0], Ah[mi][1], Ah[mi][2], Ah[mi][3],
                             Bh[ni][0], Bh[ni][1]);
                    mma_bf16(d[0], d[1], d[2], d[3],
                             Ah[mi][0], Ah[mi][1], Ah[mi][2], Ah[mi][3],
                             Bl[ni][0], Bl[ni][1]);
                    mma_bf16(d[0], d[1], d[2], d[3],
                             Al[mi][0], Al[mi][1], Al[mi][2], Al[mi][3],
                             Bh[ni][0], Bh[ni][1]);
                }
        }
        __syncthreads();
    }

    float cs[4][2], cq[4][2];
#pragma unroll
    for (int ni = 0; ni < 4; ni++) {
        cs[ni][0] = cs[ni][1] = 0.f;
        cq[ni][0] = cq[ni][1] = 0.f;
    }
#pragma unroll
    for (int ni = 0; ni < 4; ni++) {
        int col = ng * 32 + ni * 8 + 2 * tg;
#pragma unroll
        for (int mi = 0; mi < 2; mi++) {
            int gr = r0 + mg * 32 + mi * 16 + gid;
            if (gr < NN) {
                float v0 = acc[mi][ni][0], v1 = acc[mi][ni][1];
                *(float2*)(out + (long)gr * DD + col) = make_float2(v0, v1);
                cs[ni][0] += v0; cq[ni][0] += v0 * v0;
                cs[ni][1] += v1; cq[ni][1] += v1 * v1;
            }
            int gr8 = gr + 8;
            if (gr8 < NN) {
                float v2 = acc[mi][ni][2], v3 = acc[mi][ni][3];
                *(float2*)(out + (long)gr8 * DD + col) = make_float2(v2, v3);
                cs[ni][0] += v2; cq[ni][0] += v2 * v2;
                cs[ni][1] += v3; cq[ni][1] += v3 * v3;
            }
        }
    }
    __syncthreads();
    float* ssum = (float*)smu;
    float* ssq  = (float*)smu + 128;
    if (tid < 256) ((float*)smu)[tid] = 0.f;
    __syncthreads();
#pragma unroll
    for (int ni = 0; ni < 4; ni++) {
        int col = ng * 32 + ni * 8 + 2 * tg;
        atomicAdd(&ssum[col], cs[ni][0]);
        atomicAdd(&ssum[col + 1], cs[ni][1]);
        atomicAdd(&ssq[col], cq[ni][0]);
        atomicAdd(&ssq[col + 1], cq[ni][1]);
    }
    __syncthreads();
    if (tid < 128) {
        atomicAdd(&stat[tid], ssum[tid]);
        atomicAdd(&stat[128 + tid], ssq[tid]);
    }

    __shared__ int lastblk;
    __threadfence();
    __syncthreads();
    if (tid == 0) {
        int old = atomicAdd(&syn[4], 1);
        lastblk = (old == (int)gridDim.x - 1);
    }
    __syncthreads();
    if (lastblk && tid < 128) {
        float s  = atomicAdd(&stat[tid], 0.f);
        float sq = atomicAdd(&stat[128 + tid], 0.f);
        float mu  = s * (1.f / NN);
        float var = sq * (1.f / NN) - mu * mu;
        float sc  = __ldg(gamma + tid) * rsqrtf(var + 1e-5f);
        bn[tid]       = sc;
        bn[128 + tid] = __ldg(beta + tid) - mu * sc;
    }
}

// ---------------------------------------------------------------------------
__global__ void __launch_bounds__(256) k_mlp2(
    const float* __restrict__ H, const float* __restrict__ bn,
    const float* __restrict__ Wm2, float* __restrict__ out) {
    __shared__ float sw[256];
    __shared__ float sb[256];
    int tid = threadIdx.x;
    if (tid < 256) { sw[tid] = Wm2[tid]; sb[tid] = bn[tid]; }
    __syncthreads();
    int g = blockIdx.x * blockDim.x + tid;
    int row = g >> 5, lane = g & 31;
    if (row >= NN) return;
    float4 h = ((const float4*)(H + (long)row * DD))[lane];
    float s0 = 0.f, s1 = 0.f;
    int c = lane * 4;
    float hv[4] = {h.x, h.y, h.z, h.w};
#pragma unroll
    for (int j = 0; j < 4; j++) {
        int cc = c + j;
        float v = fmaxf(hv[j] * sb[cc] + sb[128 + cc], 0.f);
        s0 += v * sw[cc * 2];
        s1 += v * sw[cc * 2 + 1];
    }
#pragma unroll
    for (int off = 16; off > 0; off >>= 1) {
        s0 += __shfl_down_sync(0xffffffffu, s0, off);
        s1 += __shfl_down_sync(0xffffffffu, s1, off);
    }
    if (lane == 0) {
        out[row * 2]     = s0;
        out[row * 2 + 1] = s1;
    }
}

// ---------------------------------------------------------------------------
extern "C" void kernel_launch(void* const* d_in, const int* in_sizes, int n_in,
                              void* d_out, int out_size) {
    const float* xA    = (const float*)d_in[0];
    const float* xB    = (const float*)d_in[1];
    const int*   s0    = (const int*)d_in[2];
    const int*   d0    = (const int*)d_in[3];
    const int*   s1    = (const int*)d_in[4];
    const int*   d1    = (const int*)d_in[5];
    const float* W1r0  = (const float*)d_in[6];
    const float* b1r0  = (const float*)d_in[7];
    const float* W1r1  = (const float*)d_in[8];
    const float* b1r1  = (const float*)d_in[9];
    const float* W2r0  = (const float*)d_in[10];
    const float* b2r0  = (const float*)d_in[11];
    const float* W2r1  = (const float*)d_in[12];
    const float* b2r1  = (const float*)d_in[13];
    const float* Wm1   = (const float*)d_in[14];
    const float* gamma = (const float*)d_in[15];
    const float* beta  = (const float*)d_in[16];
    const float* Wm2   = (const float*)d_in[17];
    float* out = (float*)d_out;

    float* S = nullptr;
    cudaGetSymbolAddress((void**)&S, g_s);
    int* I = nullptr;
    cudaGetSymbolAddress((void**)&I, g_i);

    uint4* AGG1B = (uint4*)(S + OFF_AGG1B);
    uint4* AGG1A = (uint4*)(S + OFF_AGG1A);
    uint4* AGG2B = (uint4*)(S + OFF_AGG2B);
    uint4* AGG2A = (uint4*)(S + OFF_AGG2A);
    float* HB    = S + OFF_HB;
    float* HA    = S + OFF_HA;
    float* H2A   = S + OFF_H2A;
    float* H2B   = S + OFF_H2B;
    float* HMLP  = S + OFF_HMLP;
    float* RS    = S + OFF_RS;
    float* STATS = S + OFF_STATS;
    float* BN    = S + OFF_BN;
    unsigned* WT = (unsigned*)(S + OFF_WT);

    int* eidx0 = I + IOFF_EIDX0;
    int* eidx1 = I + IOFF_EIDX1;
    int* od0   = I + IOFF_OD0;
    int* cnt0  = I + IOFF_CNT0;
    int* od1   = I + IOFF_OD1;
    int* cnt1  = I + IOFF_CNT1;
    int* rp0   = I + IOFF_RP0;
    int* rp1   = I + IOFF_RP1;
    int* cur0  = I + IOFF_CUR0;
    int* cur1  = I + IOFF_CUR1;
    int* bsum  = I + IOFF_BSUM;
    int* pfx   = I + IOFF_PFX;
    int* syn   = I + IOFF_SYNC;

    float* rs_src0 = RS + 0 * NN;
    float* rs_dst0 = RS + 1 * NN;
    float* rs_src1 = RS + 2 * NN;
    float* rs_dst1 = RS + 3 * NN;

    unsigned* W1r0T = WT + 0;
    unsigned* W1r1T = WT + 16384;
    unsigned* W2r0T = WT + 32768;
    unsigned* W2r1T = WT + 49152;
    unsigned* Wm1T  = WT + 65536;

    cudaFuncSetAttribute(k_gemm_bf16, cudaFuncAttributeMaxDynamicSharedMemorySize, (int)SMEM_G);
    cudaFuncSetAttribute(k_mlp1_bf16, cudaFuncAttributeMaxDynamicSharedMemorySize, (int)SMEM_G);

    cudaStream_t sB;
    cudaStreamCreateWithFlags(&sB, cudaStreamNonBlocking);
    cudaEvent_t evZero, evHA, evHB, evDone;
    cudaEventCreateWithFlags(&evZero, cudaEventDisableTiming);
    cudaEventCreateWithFlags(&evHA, cudaEventDisableTiming);
    cudaEventCreateWithFlags(&evHB, cudaEventDisableTiming);
    cudaEventCreateWithFlags(&evDone, cudaEventDisableTiming);

    int egrid = (EE + 255) / 256;
    int ggrid = (NN * 32 + 255) / 256;
    int tgrid = (NN + 63) / 64;
    int mgrid = (NN + 63) / 64;

    // ---- stream B: wprep first ----
    k_wprep<<<192, 256, 0, sB>>>(W1r0, W1r1, W2r0, W2r1, Wm1, WT);

    // ---- stream 0: zero, then fork ----
    k_zero2<<<(NN + 255) / 256, 256>>>(od0, STATS, syn);
    cudaEventRecord(evZero, 0);
    cudaStreamWaitEvent(sB, evZero, 0);

    // ---- relation-0 setup on stream 0 ----
    k_hist_r<<<egrid, 256>>>(s0, d0, od0, cnt0);
    k_scan_r<<<NBLK, 256>>>(cnt0, od0, bsum, pfx, &syn[0], &syn[1],
                            rp0, cur0, rs_src0, rs_dst0);
    k_fill_r<<<egrid, 256>>>(s0, d0, cur0, eidx0);

    // ---- relation-1 setup on stream B ----
    k_hist_r<<<egrid, 256, 0, sB>>>(s1, d1, od1, cnt1);
    k_scan_r<<<NBLK, 256, 0, sB>>>(cnt1, od1, bsum + NBLK, pfx + NBLK,
                                   &syn[2], &syn[3], rp1, cur1, rs_src1, rs_dst1);
    k_fill_r<<<egrid, 256, 0, sB>>>(s1, d1, cur1, eidx1);

    // ---- conv1 relation 0 (stream 0); no cross-stream scan wait ----
    k_gather_pk<<<ggrid, 256>>>(xA, eidx0, rp0, rs_src0, rs_dst0, AGG1B, 1);
    k_gemm_bf16<<<tgrid, 256, SMEM_G>>>(AGG1B, W1r0T, b1r0, HB, nullptr, 1);
    cudaEventRecord(evHB, 0);

    // ---- conv1 relation 1 (stream B); no cross-stream scan wait ----
    k_gather_pk<<<ggrid, 256, 0, sB>>>(xB, eidx1, rp1, rs_src1, rs_dst1, AGG1A, 1);
    k_gemm_bf16<<<tgrid, 256, SMEM_G, sB>>>(AGG1A, W1r1T, b1r1, HA, nullptr, 1);
    cudaEventRecord(evHA, sB);

    // ---- conv2 relation 0 (stream 0, needs HA): rs_src0 applied per edge ----
    cudaStreamWaitEvent(0, evHA, 0);
    k_gather_pk<<<ggrid, 256>>>(HA, eidx0, rp0, rs_src0, rs_dst0, AGG2B, 1);
    k_gemm_bf16<<<tgrid, 256, SMEM_G>>>(AGG2B, W2r0T, b2r0, H2B, nullptr, 0);

    // ---- conv2 relation 1 (stream B, needs HB): rs_src1 applied per edge ----
    cudaStreamWaitEvent(sB, evHB, 0);
    k_gather_pk<<<ggrid, 256, 0, sB>>>(HB, eidx1, rp1, rs_src1, rs_dst1, AGG2A, 1);
    k_gemm_bf16<<<tgrid, 256, SMEM_G, sB>>>(AGG2A, W2r1T, b2r1, H2A, nullptr, 0);
    cudaEventRecord(evDone, sB);

    // ---- join, MLP head ----
    cudaStreamWaitEvent(0, evDone, 0);
    k_mlp1_bf16<<<mgrid, 256, SMEM_G>>>(H2A, H2B, Wm1T, HMLP, STATS, syn,
                                        gamma, beta, BN);
    k_mlp2<<<(NN * 32 + 255) / 256, 256>>>(HMLP, BN, Wm2, out);
}